// round 1
// baseline (speedup 1.0000x reference)
#include <cuda_runtime.h>
#include <cuda_bf16.h>
#include <cstdint>

#define BATCH 4096
#define NVIEW 2
#define DIM   512
#define NTOT  8192

#define M_TILE 128
#define N_TILE 128
#define KC     128

#define A_STRIDE 520              // bf16 elems per As row (512 + 8 pad -> 1040B, conflict-free ldmatrix)
#define B_STRIDE 136              // bf16 elems per Bs row (128 + 8 pad -> 272B)

#define SMEM_AS_BYTES (M_TILE * A_STRIDE * 2)          // 133120
#define SMEM_BS_BYTES (N_TILE * B_STRIDE * 2)          // 34816
#define OFF_BS  SMEM_AS_BYTES                          // 133120
#define OFF_LS  (OFF_BS + 2 * SMEM_BS_BYTES)           // 202752
#define OFF_RED (OFF_LS + 2 * 128 * 4)                 // 203776
#define SMEM_TOTAL (OFF_RED + 2 * 128 * 3 * 4)         // 206848

#define C_EXP  20.60992915555662f   // log2(e)/0.07
#define INV_T  14.285714285714286f  // 1/0.07

// ------------------------- scratch (no allocations allowed) -------------------------
__device__ __nv_bfloat16 g_A[(size_t)NTOT * DIM];
__device__ float g_Z[2][NTOT];
__device__ float g_S[2][NTOT];
__device__ float g_C[2][NTOT];

// ------------------------- small PTX helpers -------------------------
__device__ __forceinline__ void cp16(uint32_t saddr, const void* g) {
    asm volatile("cp.async.cg.shared.global [%0], [%1], 16;" :: "r"(saddr), "l"(g));
}
__device__ __forceinline__ void cp_commit() { asm volatile("cp.async.commit_group;"); }
template<int N> __device__ __forceinline__ void cp_wait() {
    asm volatile("cp.async.wait_group %0;" :: "n"(N));
}
__device__ __forceinline__ void ldm4(uint32_t r[4], uint32_t addr) {
    asm volatile("ldmatrix.sync.aligned.m8n8.x4.shared.b16 {%0,%1,%2,%3}, [%4];"
        : "=r"(r[0]), "=r"(r[1]), "=r"(r[2]), "=r"(r[3]) : "r"(addr));
}
__device__ __forceinline__ void mma16816(float c[4], const uint32_t a[4], const uint32_t b[2]) {
    asm volatile("mma.sync.aligned.m16n8k16.row.col.f32.bf16.bf16.f32 "
        "{%0,%1,%2,%3}, {%4,%5,%6,%7}, {%8,%9}, {%0,%1,%2,%3};"
        : "+f"(c[0]), "+f"(c[1]), "+f"(c[2]), "+f"(c[3])
        : "r"(a[0]), "r"(a[1]), "r"(a[2]), "r"(a[3]), "r"(b[0]), "r"(b[1]));
}

// ------------------------- kernel 1: normalize + view-swap -> bf16 -------------------------
__global__ void norm_kernel(const float* __restrict__ feats) {
    int warp = threadIdx.x >> 5, lane = threadIdx.x & 31;
    int row  = blockIdx.x * 8 + warp;        // row of contrast_feature
    int b = row & (BATCH - 1);
    int v = row >> 12;                       // row = v*BATCH + b
    const float4* src = reinterpret_cast<const float4*>(feats + (size_t)(b * NVIEW + v) * DIM);
    float4 f[4];
    float ss = 0.f;
#pragma unroll
    for (int q = 0; q < 4; q++) {
        f[q] = src[lane + 32 * q];
        ss += f[q].x * f[q].x + f[q].y * f[q].y + f[q].z * f[q].z + f[q].w * f[q].w;
    }
#pragma unroll
    for (int o = 16; o; o >>= 1) ss += __shfl_xor_sync(0xffffffffu, ss, o);
    float sc = 1.0f / fmaxf(sqrtf(ss), 1e-8f);
    uint2* dst = reinterpret_cast<uint2*>(g_A + (size_t)row * DIM);
#pragma unroll
    for (int q = 0; q < 4; q++) {
        __nv_bfloat162 p0 = __floats2bfloat162_rn(f[q].x * sc, f[q].y * sc);
        __nv_bfloat162 p1 = __floats2bfloat162_rn(f[q].z * sc, f[q].w * sc);
        uint2 pk;
        pk.x = *reinterpret_cast<uint32_t*>(&p0);
        pk.y = *reinterpret_cast<uint32_t*>(&p1);
        dst[lane + 32 * q] = pk;
    }
}

// ------------------------- kernel 2: fused GEMM + epilogue -------------------------
__device__ __forceinline__ void prefetch_chunk(uint32_t sbase, char* /*unused*/, int t, int c,
                                               int buf, int col_base, const int* labels) {
    int jt = c >> 2;                       // 4 k-chunks of 128 per 128-col tile
    int j0 = col_base + jt * N_TILE;
    int k0 = (c & 3) * KC;
#pragma unroll
    for (int s = 0; s < 8; s++) {          // 2048 16B segs / 256 threads
        int f = t + 256 * s;
        int row = f >> 4, seg = f & 15;
        const void* src = g_A + (size_t)(j0 + row) * DIM + k0 + seg * 8;
        uint32_t dst = sbase + OFF_BS + buf * SMEM_BS_BYTES + row * (B_STRIDE * 2) + seg * 16;
        cp16(dst, src);
    }
    if ((c & 3) == 0 && t < 32) {          // labels for the tile (double-buffered)
        const void* src = labels + ((j0 + t * 4) & (BATCH - 1));
        uint32_t dst = sbase + OFF_LS + (jt & 1) * 512 + t * 16;
        cp16(dst, src);
    }
}

__global__ void __launch_bounds__(256, 1) supcon_main(const int* __restrict__ labels) {
    extern __shared__ char smem[];
    const int t = threadIdx.x, lane = t & 31, wid = t >> 5;
    const int warp_m = wid >> 1, warp_n = wid & 1;
    const int row_base = blockIdx.x * M_TILE;
    const int col_base = blockIdx.y * (NTOT / 2);
    const uint32_t sbase = (uint32_t)__cvta_generic_to_shared(smem);

    // ---- load full-K A tile (128 x 512 bf16) once ----
    for (int f = t; f < 128 * 64; f += 256) {      // 64 x 16B segs per row
        int row = f >> 6, seg = f & 63;
        uint4 v = *reinterpret_cast<const uint4*>(g_A + (size_t)(row_base + row) * DIM + seg * 8);
        *reinterpret_cast<uint4*>(smem + row * (A_STRIDE * 2) + seg * 16) = v;
    }

    // per-thread ldmatrix base addresses
    const uint32_t as_addr = sbase + (((warp_m * 32 + (lane & 15)) * A_STRIDE + (lane >> 4) * 8) * 2);
    const uint32_t bs_lane = (((lane & 7) + ((lane >> 4) & 1) * 8) * (B_STRIDE * 2)) + ((lane >> 3) & 1) * 16
                             + warp_n * (64 * B_STRIDE * 2);

    // labels of my 4 rows
    int labi[4];
#pragma unroll
    for (int m = 0; m < 2; m++)
#pragma unroll
        for (int h = 0; h < 2; h++) {
            int ig = row_base + warp_m * 32 + m * 16 + (lane >> 2) + h * 8;
            labi[m * 2 + h] = labels[ig & (BATCH - 1)];
        }

    float acc[2][8][4];
#pragma unroll
    for (int m = 0; m < 2; m++)
#pragma unroll
        for (int n = 0; n < 8; n++)
#pragma unroll
            for (int r = 0; r < 4; r++) acc[m][n][r] = 0.f;
    float zs[4] = {0.f, 0.f, 0.f, 0.f}, ssm[4] = {0.f, 0.f, 0.f, 0.f}, cn[4] = {0.f, 0.f, 0.f, 0.f};

    __syncthreads();   // A tile visible

    const int NCHUNK = (NTOT / 2 / N_TILE) * 4;    // 32 tiles * 4 chunks = 128
    prefetch_chunk(sbase, smem, t, 0, 0, col_base, labels);
    cp_commit();

    for (int c = 0; c < NCHUNK; c++) {
        int buf = c & 1;
        if (c + 1 < NCHUNK) {
            prefetch_chunk(sbase, smem, t, c + 1, buf ^ 1, col_base, labels);
            cp_commit();
            cp_wait<1>();
        } else {
            cp_wait<0>();
        }
        __syncthreads();

        const uint32_t bbase = sbase + OFF_BS + buf * SMEM_BS_BYTES + bs_lane;
        const int kchunk = (c & 3) * KC;
#pragma unroll
        for (int ks = 0; ks < 8; ks++) {
            int kk = kchunk + ks * 16;
            uint32_t a[2][4];
            ldm4(a[0], as_addr + kk * 2);
            ldm4(a[1], as_addr + kk * 2 + 16 * A_STRIDE * 2);
            uint32_t b[8][2];
#pragma unroll
            for (int p = 0; p < 4; p++) {
                uint32_t r4[4];
                ldm4(r4, bbase + p * (16 * B_STRIDE * 2) + ks * 32);
                b[2 * p][0] = r4[0]; b[2 * p][1] = r4[1];
                b[2 * p + 1][0] = r4[2]; b[2 * p + 1][1] = r4[3];
            }
#pragma unroll
            for (int m = 0; m < 2; m++)
#pragma unroll
                for (int n = 0; n < 8; n++) mma16816(acc[m][n], a[m], b[n]);
        }

        if ((c & 3) == 3) {            // tile finished -> epilogue
            int jt = c >> 2;
            const int* Ls = reinterpret_cast<const int*>(smem + OFF_LS + (jt & 1) * 512);
            int j0 = col_base + jt * N_TILE + warp_n * 64;
#pragma unroll
            for (int m = 0; m < 2; m++) {
                int ig0 = row_base + warp_m * 32 + m * 16 + (lane >> 2);
#pragma unroll
                for (int n = 0; n < 8; n++) {
                    int jc = n * 8 + (lane & 3) * 2;
#pragma unroll
                    for (int r = 0; r < 4; r++) {
                        int h = r >> 1;
                        int ig = ig0 + h * 8;
                        int jl = jc + (r & 1);
                        int jg = j0 + jl;
                        int lj = Ls[warp_n * 64 + jl];
                        float d = acc[m][n][r];
                        float e = exp2f(d * C_EXP);
                        bool nd = (ig != jg);
                        bool pm = nd && (lj == labi[m * 2 + h]);
                        zs[m * 2 + h] += nd ? e : 0.f;
                        ssm[m * 2 + h] += pm ? d : 0.f;
                        cn[m * 2 + h] += pm ? 1.f : 0.f;
                        acc[m][n][r] = 0.f;
                    }
                }
            }
        }
        __syncthreads();
    }

    // ---- reduce: across quad lanes, then across warp_n via smem ----
#pragma unroll
    for (int r = 0; r < 4; r++) {
        zs[r] += __shfl_xor_sync(0xffffffffu, zs[r], 1);
        zs[r] += __shfl_xor_sync(0xffffffffu, zs[r], 2);
        ssm[r] += __shfl_xor_sync(0xffffffffu, ssm[r], 1);
        ssm[r] += __shfl_xor_sync(0xffffffffu, ssm[r], 2);
        cn[r] += __shfl_xor_sync(0xffffffffu, cn[r], 1);
        cn[r] += __shfl_xor_sync(0xffffffffu, cn[r], 2);
    }
    float* red = reinterpret_cast<float*>(smem + OFF_RED);   // [2][128][3]
    __syncthreads();
    if ((lane & 3) == 0) {
        int g = lane >> 2;
#pragma unroll
        for (int m = 0; m < 2; m++)
#pragma unroll
            for (int h = 0; h < 2; h++) {
                int rl = warp_m * 32 + m * 16 + h * 8 + g;
                int base = (warp_n * 128 + rl) * 3;
                red[base + 0] = zs[m * 2 + h];
                red[base + 1] = ssm[m * 2 + h];
                red[base + 2] = cn[m * 2 + h];
            }
    }
    __syncthreads();
    if (t < 128) {
        float Z = red[t * 3 + 0] + red[(128 + t) * 3 + 0];
        float S = red[t * 3 + 1] + red[(128 + t) * 3 + 1];
        float C = red[t * 3 + 2] + red[(128 + t) * 3 + 2];
        int row = row_base + t;
        g_Z[blockIdx.y][row] = Z;
        g_S[blockIdx.y][row] = S;
        g_C[blockIdx.y][row] = C;
    }
}

// ------------------------- kernel 3: finalize -------------------------
__global__ void finalize_kernel(float* __restrict__ out) {
    __shared__ float sred[256];
    int t = threadIdx.x;
    float acc = 0.f;
    for (int r = t; r < NTOT; r += 256) {
        float Z = g_Z[0][r] + g_Z[1][r];
        float S = (g_S[0][r] + g_S[1][r]) * INV_T;
        float C = g_C[0][r] + g_C[1][r];
        acc += (S - C * logf(Z + 1e-8f)) / (C + 1e-8f);
    }
    sred[t] = acc;
    __syncthreads();
    for (int o = 128; o; o >>= 1) {
        if (t < o) sred[t] += sred[t + o];
        __syncthreads();
    }
    if (t == 0) out[0] = -sred[0] / (float)NTOT;
}

// ------------------------- launch -------------------------
extern "C" void kernel_launch(void* const* d_in, const int* in_sizes, int n_in,
                              void* d_out, int out_size) {
    const float* feats = (const float*)d_in[0];
    const int* labels = (const int*)d_in[1];
    (void)in_sizes; (void)n_in; (void)out_size;

    cudaFuncSetAttribute(supcon_main, cudaFuncAttributeMaxDynamicSharedMemorySize, SMEM_TOTAL);

    norm_kernel<<<NTOT / 8, 256>>>(feats);
    supcon_main<<<dim3(NTOT / M_TILE, 2), 256, SMEM_TOTAL>>>(labels);
    finalize_kernel<<<1, 256>>>((float*)d_out);
}